// round 11
// baseline (speedup 1.0000x reference)
#include <cuda_runtime.h>
#include <cuda_bf16.h>
#include <stdint.h>

#define NTOK 4096
#define CINC 256
#define COC  128
#define BQ   128
#define BK   64
#define NKT  (NTOK / BK)

// ------------------------- scratch (__device__ globals) ---------------------
__device__ float d_proj[4 * 384 * NTOK];
__device__ float d_y[4 * COC * NTOK];
__device__ __nv_bfloat16 d_th_hi[4 * NTOK * COC];
__device__ __nv_bfloat16 d_th_lo[4 * NTOK * COC];
__device__ __nv_bfloat16 d_ph_hi[4 * NTOK * COC];
__device__ __nv_bfloat16 d_ph_lo[4 * NTOK * COC];
__device__ __nv_bfloat16 d_g_hi [4 * COC * NTOK];
__device__ __nv_bfloat16 d_g_lo [4 * COC * NTOK];
__device__ __nv_bfloat16 d_xt_hi[4 * NTOK * CINC];   // x transposed [b][n][c]
__device__ __nv_bfloat16 d_xt_lo[4 * NTOK * CINC];
__device__ __nv_bfloat16 d_w_hi[3 * 32768];          // [theta|phi|g] weights
__device__ __nv_bfloat16 d_w_lo[3 * 32768];

// ------------------------- helpers ------------------------------------------
__device__ __forceinline__ uint32_t smem_u32(const void* p) {
    uint32_t a;
    asm("{ .reg .u64 t; cvta.to.shared.u64 t, %1; cvt.u32.u64 %0, t; }" : "=r"(a) : "l"(p));
    return a;
}
#define CPA(dst, src) asm volatile("cp.async.cg.shared.global [%0], [%1], 16;" :: "r"(dst), "l"(src) : "memory")
#define CPC()  asm volatile("cp.async.commit_group;" ::: "memory")
#define CPW1() asm volatile("cp.async.wait_group 1;" ::: "memory")
#define CPW0() asm volatile("cp.async.wait_group 0;" ::: "memory")

__device__ __forceinline__ void ldsm4(uint32_t* r, uint32_t a) {
    asm volatile("ldmatrix.sync.aligned.m8n8.x4.shared.b16 {%0,%1,%2,%3}, [%4];"
        : "=r"(r[0]), "=r"(r[1]), "=r"(r[2]), "=r"(r[3]) : "r"(a));
}
// NOTE: non-volatile — pure register op, lets the compiler interleave MMA chains
__device__ __forceinline__ void mma16816(float* c, const uint32_t* a, uint32_t b0, uint32_t b1) {
    asm("mma.sync.aligned.m16n8k16.row.col.f32.bf16.bf16.f32 "
        "{%0,%1,%2,%3}, {%4,%5,%6,%7}, {%8,%9}, {%0,%1,%2,%3};"
        : "+f"(c[0]), "+f"(c[1]), "+f"(c[2]), "+f"(c[3])
        : "r"(a[0]), "r"(a[1]), "r"(a[2]), "r"(a[3]), "r"(b0), "r"(b1));
}
__device__ __forceinline__ uint32_t pack_bf16_hi(float x, float y) {
    __nv_bfloat162 h = __floats2bfloat162_rn(x, y);
    return *(uint32_t*)&h;
}

// ---------------------------------------------------------------------------
// Weight split: wt/wp/wg fp32 -> bf16 hi/lo
// ---------------------------------------------------------------------------
__global__ __launch_bounds__(256) void wsplit(
    const float* __restrict__ wt, const float* __restrict__ wp,
    const float* __restrict__ wg)
{
    int i = blockIdx.x * 256 + threadIdx.x;     // < 98304
    float v;
    if (i < 32768)       v = wt[i];
    else if (i < 65536)  v = wp[i - 32768];
    else                 v = wg[i - 65536];
    __nv_bfloat16 h = __float2bfloat16(v);
    d_w_hi[i] = h;
    d_w_lo[i] = __float2bfloat16(v - __bfloat162float(h));
}

// ---------------------------------------------------------------------------
// x transpose+split: x [b][c][n] fp32 -> xt hi/lo [b][n][c] bf16
// ---------------------------------------------------------------------------
__global__ __launch_bounds__(256) void xsplit(const float* __restrict__ x)
{
    __shared__ float s[128][65];
    int b = blockIdx.z, ch = blockIdx.y, n0 = blockIdx.x * 64;
    const float* src = x + ((size_t)b * CINC + ch * 128) * NTOK;
    int tid = threadIdx.x;
    #pragma unroll
    for (int it = 0; it < 8; it++) {
        int idx = tid + it * 256;
        int c = idx >> 4, n = (idx & 15) * 4;
        float4 v = *(const float4*)&src[(size_t)c * NTOK + n0 + n];
        s[c][n] = v.x; s[c][n+1] = v.y; s[c][n+2] = v.z; s[c][n+3] = v.w;
    }
    __syncthreads();
    #pragma unroll
    for (int it = 0; it < 16; it++) {
        int idx = tid + it * 256;
        int t = idx >> 6, cp = idx & 63;
        int c = cp * 2;
        float v0 = s[c][t], v1 = s[c+1][t];
        __nv_bfloat16 h0 = __float2bfloat16(v0), h1 = __float2bfloat16(v1);
        __nv_bfloat162 hp; hp.x = h0; hp.y = h1;
        __nv_bfloat162 lp = __floats2bfloat162_rn(v0 - __bfloat162float(h0),
                                                  v1 - __bfloat162float(h1));
        size_t base = ((size_t)b * NTOK + n0 + t) * CINC + ch * 128 + c;
        *(__nv_bfloat162*)&d_xt_hi[base] = hp;
        *(__nv_bfloat162*)&d_xt_lo[base] = lp;
    }
}

// ---------------------------------------------------------------------------
// Tensor-core projection: d_proj[b][pr*128+row][n] = W[row][:]·x[:, n] + bias
// CTA: 128 rows x 128 tokens, K=256 in 16-wide chunks, bf16 3-split mma.
// smem: 2 bufs x 4 mats (Whi,Wlo,Xhi,Xlo) x (128 rows x 48B) = 49152 B
// ---------------------------------------------------------------------------
__global__ __launch_bounds__(256) void gemm_proj(
    const float* __restrict__ bt, const float* __restrict__ bp,
    const float* __restrict__ bg)
{
    extern __shared__ char smg[];
    uint32_t sb = smem_u32(smg);
    int tid = threadIdx.x, w = tid >> 5, lane = tid & 31;
    int wm = w >> 2, wn = w & 3;
    int n0 = blockIdx.x * 128, pr = blockIdx.y, b = blockIdx.z;
    const float* bias = (pr == 0) ? bt : (pr == 1) ? bp : bg;

    const __nv_bfloat16* wh = d_w_hi + pr * 32768;
    const __nv_bfloat16* wl = d_w_lo + pr * 32768;
    const __nv_bfloat16* xh = d_xt_hi + ((size_t)b * NTOK + n0) * CINC;
    const __nv_bfloat16* xl = d_xt_lo + ((size_t)b * NTOK + n0) * CINC;

    int lrow = tid >> 1, lhalf = tid & 1;
    auto loadchunk = [&](int kc, int buf) {
        uint32_t base = sb + buf * 24576u + lrow * 48 + lhalf * 16;
        size_t off = (size_t)lrow * CINC + kc * 16 + lhalf * 8;
        CPA(base,         wh + off);
        CPA(base + 6144,  wl + off);
        CPA(base + 12288, xh + off);
        CPA(base + 18432, xl + off);
        CPC();
    };

    float acc[4][4][4] = {};
    uint32_t aAddr = (wm * 64 + (lane & 15)) * 48 + ((lane >> 4) & 1) * 16;
    uint32_t bRow  = (lane & 7) + ((lane & 16) >> 1);
    uint32_t bCol  = (lane & 8) * 2;

    loadchunk(0, 0);
    #pragma unroll 1
    for (int c = 0; c < 16; c++) {
        if (c + 1 < 16) { loadchunk(c + 1, (c + 1) & 1); CPW1(); }
        else            { CPW0(); }
        __syncthreads();

        uint32_t P = sb + (c & 1) * 24576u;
        uint32_t ah[4][4], al[4][4], bh[2][4], bl[2][4];
        #pragma unroll
        for (int am = 0; am < 4; am++) {
            ldsm4(ah[am], P + aAddr + am * 768);
            ldsm4(al[am], P + 6144 + aAddr + am * 768);
        }
        #pragma unroll
        for (int bn = 0; bn < 2; bn++) {
            uint32_t ba = (wn * 32 + bn * 16 + bRow) * 48 + bCol;
            ldsm4(bh[bn], P + 12288 + ba);
            ldsm4(bl[bn], P + 18432 + ba);
        }
        #pragma unroll
        for (int am = 0; am < 4; am++)
            #pragma unroll
            for (int bn = 0; bn < 2; bn++) {
                mma16816(acc[am][2*bn],   ah[am], bh[bn][0], bh[bn][1]);
                mma16816(acc[am][2*bn],   ah[am], bl[bn][0], bl[bn][1]);
                mma16816(acc[am][2*bn],   al[am], bh[bn][0], bh[bn][1]);
                mma16816(acc[am][2*bn+1], ah[am], bh[bn][2], bh[bn][3]);
                mma16816(acc[am][2*bn+1], ah[am], bl[bn][2], bl[bn][3]);
                mma16816(acc[am][2*bn+1], al[am], bh[bn][2], bh[bn][3]);
            }
        __syncthreads();
    }

    // epilogue: bias + write fp32 [row][n]
    float* dst = d_proj + ((size_t)b * 384 + pr * 128) * NTOK;
    int r0 = wm * 64 + (lane >> 2);
    int c0 = wn * 32 + (lane & 3) * 2;
    #pragma unroll
    for (int am = 0; am < 4; am++) {
        int ra = r0 + am * 16;
        float b0 = bias[ra], b1 = bias[ra + 8];
        #pragma unroll
        for (int nf = 0; nf < 4; nf++) {
            int col = n0 + c0 + nf * 8;
            *(float2*)&dst[(size_t)ra * NTOK + col] =
                make_float2(acc[am][nf][0] + b0, acc[am][nf][1] + b0);
            *(float2*)&dst[(size_t)(ra + 8) * NTOK + col] =
                make_float2(acc[am][nf][2] + b1, acc[am][nf][3] + b1);
        }
    }
}

// ---------------------------------------------------------------------------
// Convert theta/phi: fp32 [c][n] -> bf16 hi/lo [n][c]   (transpose + split)
// ---------------------------------------------------------------------------
__global__ __launch_bounds__(256) void convert_tp()
{
    __shared__ float sm[128][65];
    int b = blockIdx.z;
    int pr = blockIdx.y;
    int n0 = blockIdx.x * 64;
    const float* src = d_proj + ((size_t)b * 384 + pr * 128) * NTOK;
    __nv_bfloat16* dh = (pr == 0 ? d_th_hi : d_ph_hi);
    __nv_bfloat16* dl = (pr == 0 ? d_th_lo : d_ph_lo);
    int tid = threadIdx.x;

    #pragma unroll
    for (int it = 0; it < 8; it++) {
        int idx = tid + it * 256;
        int c = idx >> 4, n = (idx & 15) * 4;
        float4 v = *(const float4*)&src[(size_t)c * NTOK + n0 + n];
        sm[c][n+0] = v.x; sm[c][n+1] = v.y; sm[c][n+2] = v.z; sm[c][n+3] = v.w;
    }
    __syncthreads();
    #pragma unroll
    for (int it = 0; it < 16; it++) {
        int idx = tid + it * 256;
        int t = idx >> 6, cp = idx & 63;
        int c = cp * 2;
        float v0 = sm[c][t], v1 = sm[c+1][t];
        __nv_bfloat16 h0 = __float2bfloat16(v0), h1 = __float2bfloat16(v1);
        __nv_bfloat162 hp; hp.x = h0; hp.y = h1;
        __nv_bfloat162 lp = __floats2bfloat162_rn(v0 - __bfloat162float(h0),
                                                  v1 - __bfloat162float(h1));
        size_t base = ((size_t)b * NTOK + n0 + t) * COC + c;
        *(__nv_bfloat162*)&dh[base] = hp;
        *(__nv_bfloat162*)&dl[base] = lp;
    }
}

// ---------------------------------------------------------------------------
// Convert g: fp32 [co][n] -> bf16 hi/lo [co][n]   (split only)
// ---------------------------------------------------------------------------
__global__ __launch_bounds__(256) void convert_g()
{
    size_t e0 = ((size_t)blockIdx.x * 256 + threadIdx.x) * 8;
    int b = (int)(e0 >> 19);
    size_t within = e0 & 524287;
    const float* s = d_proj + (size_t)b * 1572864 + 1048576 + within;
    float v[8];
    *(float4*)&v[0] = *(const float4*)&s[0];
    *(float4*)&v[4] = *(const float4*)&s[4];
    uint32_t h[4], l[4];
    #pragma unroll
    for (int i = 0; i < 4; i++) {
        __nv_bfloat16 h0 = __float2bfloat16(v[2*i]), h1 = __float2bfloat16(v[2*i+1]);
        __nv_bfloat162 hp; hp.x = h0; hp.y = h1;
        __nv_bfloat162 lp = __floats2bfloat162_rn(v[2*i] - __bfloat162float(h0),
                                                  v[2*i+1] - __bfloat162float(h1));
        h[i] = *(uint32_t*)&hp; l[i] = *(uint32_t*)&lp;
    }
    *(uint4*)&d_g_hi[e0] = make_uint4(h[0], h[1], h[2], h[3]);
    *(uint4*)&d_g_lo[e0] = make_uint4(l[0], l[1], l[2], l[3]);
}

// ---------------------------------------------------------------------------
// Flash attention via mma.sync bf16 hi/lo 3-split, fixed-shift softmax.
// ---------------------------------------------------------------------------
#define SM_TH_HI  0u
#define SM_TH_LO  34816u
#define SM_PH     69632u
#define SM_G      139264u
#define SM_LARR   212992u
#define SM_BYTES  213504

__global__ __launch_bounds__(256, 1) void attn_kernel()
{
    extern __shared__ char sm[];
    uint32_t sb = smem_u32(sm);
    int tid = threadIdx.x, w = tid >> 5, lane = tid & 31;
    int b = blockIdx.y, q0 = blockIdx.x * BQ;

    const __nv_bfloat16* thh = d_th_hi + ((size_t)b * NTOK + q0) * COC;
    const __nv_bfloat16* thl = d_th_lo + ((size_t)b * NTOK + q0) * COC;
    const __nv_bfloat16* phh = d_ph_hi + (size_t)b * NTOK * COC;
    const __nv_bfloat16* phl = d_ph_lo + (size_t)b * NTOK * COC;
    const __nv_bfloat16* ghh = d_g_hi + (size_t)b * COC * NTOK;
    const __nv_bfloat16* ghl = d_g_lo + (size_t)b * COC * NTOK;

    #pragma unroll
    for (int it = 0; it < 8; it++) {
        int idx = tid + it * 256;
        int r = idx >> 4, ch = idx & 15;
        uint32_t d1 = sb + SM_TH_HI + r * 272 + ch * 16;
        CPA(d1,         thh + (size_t)r * COC + ch * 8);
        CPA(d1 + 34816, thl + (size_t)r * COC + ch * 8);
    }
    #pragma unroll
    for (int it = 0; it < 4; it++) {
        int idx = tid + it * 256;
        int r = idx >> 4, ch = idx & 15;
        uint32_t d1 = sb + SM_PH + r * 272 + ch * 16;
        CPA(d1,         phh + (size_t)r * COC + ch * 8);
        CPA(d1 + 17408, phl + (size_t)r * COC + ch * 8);
        int r2 = idx >> 3, ch2 = idx & 7;
        uint32_t d2 = sb + SM_G + r2 * 144 + ch2 * 16;
        CPA(d2,         ghh + (size_t)r2 * NTOK + ch2 * 8);
        CPA(d2 + 18432, ghl + (size_t)r2 * NTOK + ch2 * 8);
    }
    CPC();

    float oacc[16][4];
    #pragma unroll
    for (int i = 0; i < 16; i++)
        #pragma unroll
        for (int j = 0; j < 4; j++) oacc[i][j] = 0.f;
    float lsum0 = 0.f, lsum1 = 0.f;

    uint32_t aaddrH = sb + SM_TH_HI + (16*w + (lane & 15)) * 272 + ((lane >> 4) & 1) * 16;
    uint32_t aaddrL = aaddrH + 34816;
    uint32_t bRow   = (lane & 7) + ((lane & 16) >> 1);
    uint32_t bColB  = (lane & 8) * 2;

    for (int kt = 0; kt < NKT; kt++) {
        if (kt + 1 < NKT) {
            int buf = (kt + 1) & 1;
            int k0 = (kt + 1) * BK;
            uint32_t phB = sb + SM_PH + buf * 34816u;
            uint32_t gB  = sb + SM_G  + buf * 36864u;
            #pragma unroll
            for (int it = 0; it < 4; it++) {
                int idx = tid + it * 256;
                int r = idx >> 4, ch = idx & 15;
                uint32_t d1 = phB + r * 272 + ch * 16;
                CPA(d1,         phh + (size_t)(k0 + r) * COC + ch * 8);
                CPA(d1 + 17408, phl + (size_t)(k0 + r) * COC + ch * 8);
                int r2 = idx >> 3, ch2 = idx & 7;
                uint32_t d2 = gB + r2 * 144 + ch2 * 16;
                CPA(d2,         ghh + (size_t)r2 * NTOK + k0 + ch2 * 8);
                CPA(d2 + 18432, ghl + (size_t)r2 * NTOK + k0 + ch2 * 8);
            }
            CPC();
            CPW1();
        } else {
            CPW0();
        }
        __syncthreads();

        int buf = kt & 1;
        uint32_t phH = sb + SM_PH + buf * 34816u;
        uint32_t phL = phH + 17408u;
        uint32_t gH  = sb + SM_G + buf * 36864u;
        uint32_t gL  = gH + 18432u;

        float sacc[8][4];
        #pragma unroll
        for (int i = 0; i < 8; i++)
            #pragma unroll
            for (int j = 0; j < 4; j++) sacc[i][j] = 0.f;

        #pragma unroll
        for (int kc = 0; kc < 8; kc++) {
            uint32_t ah[4], al[4];
            ldsm4(ah, aaddrH + kc * 32);
            ldsm4(al, aaddrL + kc * 32);
            #pragma unroll
            for (int np = 0; np < 4; np++) {
                uint32_t bh[4], bl[4];
                uint32_t ba = (16 * np + bRow) * 272 + bColB + kc * 32;
                ldsm4(bh, phH + ba);
                ldsm4(bl, phL + ba);
                mma16816(sacc[2*np],   ah, bh[0], bh[1]);
                mma16816(sacc[2*np+1], ah, bh[2], bh[3]);
                mma16816(sacc[2*np],   ah, bl[0], bl[1]);
                mma16816(sacc[2*np+1], ah, bl[2], bl[3]);
                mma16816(sacc[2*np],   al, bh[0], bh[1]);
                mma16816(sacc[2*np+1], al, bh[2], bh[3]);
            }
        }

        #pragma unroll
        for (int nf = 0; nf < 8; nf++) {
            float e0 = __expf(sacc[nf][0] - 40.f);
            float e1 = __expf(sacc[nf][1] - 40.f);
            float e2 = __expf(sacc[nf][2] - 40.f);
            float e3 = __expf(sacc[nf][3] - 40.f);
            sacc[nf][0] = e0; sacc[nf][1] = e1; sacc[nf][2] = e2; sacc[nf][3] = e3;
            lsum0 += e0 + e1;
            lsum1 += e2 + e3;
        }
        uint32_t APh[4][4], APl[4][4];
        #pragma unroll
        for (int kc = 0; kc < 4; kc++) {
            #pragma unroll
            for (int half = 0; half < 2; half++) {
                {
                    float p0 = sacc[2*kc][half*2], p1 = sacc[2*kc][half*2+1];
                    __nv_bfloat16 h0 = __float2bfloat16(p0), h1 = __float2bfloat16(p1);
                    __nv_bfloat162 hp; hp.x = h0; hp.y = h1;
                    APh[kc][half] = *(uint32_t*)&hp;
                    APl[kc][half] = pack_bf16_hi(p0 - __bfloat162float(h0),
                                                 p1 - __bfloat162float(h1));
                }
                {
                    float p0 = sacc[2*kc+1][half*2], p1 = sacc[2*kc+1][half*2+1];
                    __nv_bfloat16 h0 = __float2bfloat16(p0), h1 = __float2bfloat16(p1);
                    __nv_bfloat162 hp; hp.x = h0; hp.y = h1;
                    APh[kc][2+half] = *(uint32_t*)&hp;
                    APl[kc][2+half] = pack_bf16_hi(p0 - __bfloat162float(h0),
                                                   p1 - __bfloat162float(h1));
                }
            }
        }

        #pragma unroll
        for (int kc = 0; kc < 4; kc++) {
            #pragma unroll
            for (int np = 0; np < 8; np++) {
                uint32_t bh[4], bl[4];
                uint32_t ba = (16 * np + bRow) * 144 + bColB + kc * 32;
                ldsm4(bh, gH + ba);
                ldsm4(bl, gL + ba);
                mma16816(oacc[2*np],   APh[kc], bh[0], bh[1]);
                mma16816(oacc[2*np+1], APh[kc], bh[2], bh[3]);
                mma16816(oacc[2*np],   APh[kc], bl[0], bl[1]);
                mma16816(oacc[2*np+1], APh[kc], bl[2], bl[3]);
                mma16816(oacc[2*np],   APl[kc], bh[0], bh[1]);
                mma16816(oacc[2*np+1], APl[kc], bh[2], bh[3]);
            }
        }
        __syncthreads();
    }

    lsum0 += __shfl_xor_sync(0xffffffffu, lsum0, 1);
    lsum0 += __shfl_xor_sync(0xffffffffu, lsum0, 2);
    lsum1 += __shfl_xor_sync(0xffffffffu, lsum1, 1);
    lsum1 += __shfl_xor_sync(0xffffffffu, lsum1, 2);
    float* larr = (float*)(sm + SM_LARR);
    int gr = lane >> 2, ct = lane & 3;
    if (ct == 0) {
        larr[16*w + gr]     = lsum0;
        larr[16*w + gr + 8] = lsum1;
    }
    __syncthreads();
    float linv0 = 1.f / larr[16*w + gr];
    float linv1 = 1.f / larr[16*w + gr + 8];

    float* Ys = (float*)sm;
    #pragma unroll
    for (int nf = 0; nf < 16; nf++) {
        int co = 8 * nf + 2 * ct;
        int q  = 16 * w + gr;
        Ys[co * 132 + q]           = oacc[nf][0] * linv0;
        Ys[(co + 1) * 132 + q]     = oacc[nf][1] * linv0;
        Ys[co * 132 + q + 8]       = oacc[nf][2] * linv1;
        Ys[(co + 1) * 132 + q + 8] = oacc[nf][3] * linv1;
    }
    __syncthreads();
    float* yout = d_y + (size_t)b * COC * NTOK;
    #pragma unroll
    for (int it = 0; it < 16; it++) {
        int idx = tid + it * 256;
        int row = idx >> 5, c4 = (idx & 31) * 4;
        *(float4*)&yout[(size_t)row * NTOK + q0 + c4] = *(float4*)&Ys[row * 132 + c4];
    }
}

// ---------------------------------------------------------------------------
// Output GEMM + bias + residual
// ---------------------------------------------------------------------------
__global__ __launch_bounds__(256) void out_kernel(
    const float* __restrict__ wW, const float* __restrict__ bW,
    const float* __restrict__ x, float* __restrict__ z)
{
    __shared__ float As[16][64];
    __shared__ float Bs[16][64];
    int b    = blockIdx.z;
    int row0 = blockIdx.y * 64;
    int n0   = blockIdx.x * 64;
    int tid = threadIdx.x, ty = tid >> 4, tx = tid & 15;
    const float* Y = d_y + (size_t)b * COC * NTOK;

    float acc[4][4] = {};
    int am = tid >> 2,  ak = (tid & 3) * 4;
    int bk = tid >> 4,  bn = (tid & 15) * 4;

    for (int k0 = 0; k0 < COC; k0 += 16) {
        float4 av = *(const float4*)&wW[(row0 + am) * COC + k0 + ak];
        As[ak+0][am] = av.x; As[ak+1][am] = av.y;
        As[ak+2][am] = av.z; As[ak+3][am] = av.w;
        *(float4*)&Bs[bk][bn] = *(const float4*)&Y[(size_t)(k0 + bk) * NTOK + n0 + bn];
        __syncthreads();
        #pragma unroll
        for (int kk = 0; kk < 16; kk++) {
            float4 a = *(float4*)&As[kk][ty * 4];
            float4 v = *(float4*)&Bs[kk][tx * 4];
            acc[0][0] += a.x*v.x; acc[0][1] += a.x*v.y; acc[0][2] += a.x*v.z; acc[0][3] += a.x*v.w;
            acc[1][0] += a.y*v.x; acc[1][1] += a.y*v.y; acc[1][2] += a.y*v.z; acc[1][3] += a.y*v.w;
            acc[2][0] += a.z*v.x; acc[2][1] += a.z*v.y; acc[2][2] += a.z*v.z; acc[2][3] += a.z*v.w;
            acc[3][0] += a.w*v.x; acc[3][1] += a.w*v.y; acc[3][2] += a.w*v.z; acc[3][3] += a.w*v.w;
        }
        __syncthreads();
    }
    #pragma unroll
    for (int i = 0; i < 4; i++) {
        int r = row0 + ty * 4 + i;
        float bv = bW[r];
        float4 xv = *(const float4*)&x[((size_t)b * CINC + r) * NTOK + n0 + tx * 4];
        float4 o = make_float4(acc[i][0] + bv + xv.x, acc[i][1] + bv + xv.y,
                               acc[i][2] + bv + xv.z, acc[i][3] + bv + xv.w);
        *(float4*)&z[((size_t)b * CINC + r) * NTOK + n0 + tx * 4] = o;
    }
}

// ---------------------------------------------------------------------------
extern "C" void kernel_launch(void* const* d_in, const int* in_sizes, int n_in,
                              void* d_out, int out_size)
{
    const float* x  = (const float*)d_in[0];
    const float* wt = (const float*)d_in[1];
    const float* bt = (const float*)d_in[2];
    const float* wp = (const float*)d_in[3];
    const float* bp = (const float*)d_in[4];
    const float* wg = (const float*)d_in[5];
    const float* bg = (const float*)d_in[6];
    const float* wW = (const float*)d_in[7];
    const float* bW = (const float*)d_in[8];
    float* z = (float*)d_out;

    static int once = 0;
    if (!once) {
        cudaFuncSetAttribute(attn_kernel, cudaFuncAttributeMaxDynamicSharedMemorySize, SM_BYTES);
        cudaFuncSetAttribute(gemm_proj, cudaFuncAttributeMaxDynamicSharedMemorySize, 49152);
        once = 1;
    }

    wsplit<<<384, 256>>>(wt, wp, wg);
    xsplit<<<dim3(64, 2, 4), 256>>>(x);
    gemm_proj<<<dim3(32, 3, 4), 256, 49152>>>(bt, bp, bg);
    convert_tp<<<dim3(64, 2, 4), 256>>>();
    convert_g<<<1024, 256>>>();
    attn_kernel<<<dim3(NTOK / BQ, 4), 256, SM_BYTES>>>();
    out_kernel<<<dim3(64, 4, 4), 256>>>(wW, bW, x, z);
}

// round 12
// speedup vs baseline: 1.0082x; 1.0082x over previous
#include <cuda_runtime.h>
#include <cuda_bf16.h>
#include <stdint.h>

#define NTOK 4096
#define CINC 256
#define COC  128
#define BQ   128
#define BK   64
#define NKT  (NTOK / BK)

// ------------------------- scratch (__device__ globals) ---------------------
__device__ float d_proj[4 * 384 * NTOK];
__device__ float d_y[4 * COC * NTOK];
__device__ __nv_bfloat16 d_th_hi[4 * NTOK * COC];
__device__ __nv_bfloat16 d_th_lo[4 * NTOK * COC];
__device__ __nv_bfloat16 d_ph_hi[4 * NTOK * COC];
__device__ __nv_bfloat16 d_ph_lo[4 * NTOK * COC];
__device__ __nv_bfloat16 d_g_hi [4 * COC * NTOK];
__device__ __nv_bfloat16 d_g_lo [4 * COC * NTOK];
__device__ __nv_bfloat16 d_xt_hi[4 * NTOK * CINC];   // x transposed [b][n][c]
__device__ __nv_bfloat16 d_xt_lo[4 * NTOK * CINC];
__device__ __nv_bfloat16 d_w_hi[3 * 32768];          // [theta|phi|g] weights
__device__ __nv_bfloat16 d_w_lo[3 * 32768];

// ------------------------- helpers ------------------------------------------
__device__ __forceinline__ uint32_t smem_u32(const void* p) {
    uint32_t a;
    asm("{ .reg .u64 t; cvta.to.shared.u64 t, %1; cvt.u32.u64 %0, t; }" : "=r"(a) : "l"(p));
    return a;
}
#define CPA(dst, src) asm volatile("cp.async.cg.shared.global [%0], [%1], 16;" :: "r"(dst), "l"(src) : "memory")
#define CPC()  asm volatile("cp.async.commit_group;" ::: "memory")
#define CPW1() asm volatile("cp.async.wait_group 1;" ::: "memory")
#define CPW0() asm volatile("cp.async.wait_group 0;" ::: "memory")

__device__ __forceinline__ void ldsm4(uint32_t* r, uint32_t a) {
    asm volatile("ldmatrix.sync.aligned.m8n8.x4.shared.b16 {%0,%1,%2,%3}, [%4];"
        : "=r"(r[0]), "=r"(r[1]), "=r"(r[2]), "=r"(r[3]) : "r"(a));
}
// NOTE: non-volatile — pure register op, lets the compiler interleave MMA chains
__device__ __forceinline__ void mma16816(float* c, const uint32_t* a, uint32_t b0, uint32_t b1) {
    asm("mma.sync.aligned.m16n8k16.row.col.f32.bf16.bf16.f32 "
        "{%0,%1,%2,%3}, {%4,%5,%6,%7}, {%8,%9}, {%0,%1,%2,%3};"
        : "+f"(c[0]), "+f"(c[1]), "+f"(c[2]), "+f"(c[3])
        : "r"(a[0]), "r"(a[1]), "r"(a[2]), "r"(a[3]), "r"(b0), "r"(b1));
}
__device__ __forceinline__ uint32_t pack_bf16_hi(float x, float y) {
    __nv_bfloat162 h = __floats2bfloat162_rn(x, y);
    return *(uint32_t*)&h;
}

// ---------------------------------------------------------------------------
// Weight split: wt/wp/wg fp32 -> bf16 hi/lo
// ---------------------------------------------------------------------------
__global__ __launch_bounds__(256) void wsplit(
    const float* __restrict__ wt, const float* __restrict__ wp,
    const float* __restrict__ wg)
{
    int i = blockIdx.x * 256 + threadIdx.x;     // < 98304
    float v;
    if (i < 32768)       v = wt[i];
    else if (i < 65536)  v = wp[i - 32768];
    else                 v = wg[i - 65536];
    __nv_bfloat16 h = __float2bfloat16(v);
    d_w_hi[i] = h;
    d_w_lo[i] = __float2bfloat16(v - __bfloat162float(h));
}

// ---------------------------------------------------------------------------
// x transpose+split: x [b][c][n] fp32 -> xt hi/lo [b][n][c] bf16
// ---------------------------------------------------------------------------
__global__ __launch_bounds__(256) void xsplit(const float* __restrict__ x)
{
    __shared__ float s[128][65];
    int b = blockIdx.z, ch = blockIdx.y, n0 = blockIdx.x * 64;
    const float* src = x + ((size_t)b * CINC + ch * 128) * NTOK;
    int tid = threadIdx.x;
    #pragma unroll
    for (int it = 0; it < 8; it++) {
        int idx = tid + it * 256;
        int c = idx >> 4, n = (idx & 15) * 4;
        float4 v = *(const float4*)&src[(size_t)c * NTOK + n0 + n];
        s[c][n] = v.x; s[c][n+1] = v.y; s[c][n+2] = v.z; s[c][n+3] = v.w;
    }
    __syncthreads();
    #pragma unroll
    for (int it = 0; it < 16; it++) {
        int idx = tid + it * 256;
        int t = idx >> 6, cp = idx & 63;
        int c = cp * 2;
        float v0 = s[c][t], v1 = s[c+1][t];
        __nv_bfloat16 h0 = __float2bfloat16(v0), h1 = __float2bfloat16(v1);
        __nv_bfloat162 hp; hp.x = h0; hp.y = h1;
        __nv_bfloat162 lp = __floats2bfloat162_rn(v0 - __bfloat162float(h0),
                                                  v1 - __bfloat162float(h1));
        size_t base = ((size_t)b * NTOK + n0 + t) * CINC + ch * 128 + c;
        *(__nv_bfloat162*)&d_xt_hi[base] = hp;
        *(__nv_bfloat162*)&d_xt_lo[base] = lp;
    }
}

// ---------------------------------------------------------------------------
// Tensor-core projection: d_proj[b][pr*128+row][n] = W[row][:]·x[:, n] + bias
// CTA: 128 rows x 128 tokens, K=256 in 16-wide chunks, bf16 3-split mma.
// smem: 2 bufs x 4 mats (Whi,Wlo,Xhi,Xlo) x (128 rows x 48B) = 49152 B
// ---------------------------------------------------------------------------
__global__ __launch_bounds__(256) void gemm_proj(
    const float* __restrict__ bt, const float* __restrict__ bp,
    const float* __restrict__ bg)
{
    extern __shared__ char smg[];
    uint32_t sb = smem_u32(smg);
    int tid = threadIdx.x, w = tid >> 5, lane = tid & 31;
    int wm = w >> 2, wn = w & 3;
    int n0 = blockIdx.x * 128, pr = blockIdx.y, b = blockIdx.z;
    const float* bias = (pr == 0) ? bt : (pr == 1) ? bp : bg;

    const __nv_bfloat16* wh = d_w_hi + pr * 32768;
    const __nv_bfloat16* wl = d_w_lo + pr * 32768;
    const __nv_bfloat16* xh = d_xt_hi + ((size_t)b * NTOK + n0) * CINC;
    const __nv_bfloat16* xl = d_xt_lo + ((size_t)b * NTOK + n0) * CINC;

    int lrow = tid >> 1, lhalf = tid & 1;
    auto loadchunk = [&](int kc, int buf) {
        uint32_t base = sb + buf * 24576u + lrow * 48 + lhalf * 16;
        size_t off = (size_t)lrow * CINC + kc * 16 + lhalf * 8;
        CPA(base,         wh + off);
        CPA(base + 6144,  wl + off);
        CPA(base + 12288, xh + off);
        CPA(base + 18432, xl + off);
        CPC();
    };

    float acc[4][4][4] = {};
    uint32_t aAddr = (wm * 64 + (lane & 15)) * 48 + ((lane >> 4) & 1) * 16;
    uint32_t bRow  = (lane & 7) + ((lane & 16) >> 1);
    uint32_t bCol  = (lane & 8) * 2;

    loadchunk(0, 0);
    #pragma unroll 1
    for (int c = 0; c < 16; c++) {
        if (c + 1 < 16) { loadchunk(c + 1, (c + 1) & 1); CPW1(); }
        else            { CPW0(); }
        __syncthreads();

        uint32_t P = sb + (c & 1) * 24576u;
        uint32_t ah[4][4], al[4][4], bh[2][4], bl[2][4];
        #pragma unroll
        for (int am = 0; am < 4; am++) {
            ldsm4(ah[am], P + aAddr + am * 768);
            ldsm4(al[am], P + 6144 + aAddr + am * 768);
        }
        #pragma unroll
        for (int bn = 0; bn < 2; bn++) {
            uint32_t ba = (wn * 32 + bn * 16 + bRow) * 48 + bCol;
            ldsm4(bh[bn], P + 12288 + ba);
            ldsm4(bl[bn], P + 18432 + ba);
        }
        #pragma unroll
        for (int am = 0; am < 4; am++)
            #pragma unroll
            for (int bn = 0; bn < 2; bn++) {
                mma16816(acc[am][2*bn],   ah[am], bh[bn][0], bh[bn][1]);
                mma16816(acc[am][2*bn],   ah[am], bl[bn][0], bl[bn][1]);
                mma16816(acc[am][2*bn],   al[am], bh[bn][0], bh[bn][1]);
                mma16816(acc[am][2*bn+1], ah[am], bh[bn][2], bh[bn][3]);
                mma16816(acc[am][2*bn+1], ah[am], bl[bn][2], bl[bn][3]);
                mma16816(acc[am][2*bn+1], al[am], bh[bn][2], bh[bn][3]);
            }
        __syncthreads();
    }

    // epilogue: bias + write fp32 [row][n]
    float* dst = d_proj + ((size_t)b * 384 + pr * 128) * NTOK;
    int r0 = wm * 64 + (lane >> 2);
    int c0 = wn * 32 + (lane & 3) * 2;
    #pragma unroll
    for (int am = 0; am < 4; am++) {
        int ra = r0 + am * 16;
        float b0 = bias[ra], b1 = bias[ra + 8];
        #pragma unroll
        for (int nf = 0; nf < 4; nf++) {
            int col = n0 + c0 + nf * 8;
            *(float2*)&dst[(size_t)ra * NTOK + col] =
                make_float2(acc[am][nf][0] + b0, acc[am][nf][1] + b0);
            *(float2*)&dst[(size_t)(ra + 8) * NTOK + col] =
                make_float2(acc[am][nf][2] + b1, acc[am][nf][3] + b1);
        }
    }
}

// ---------------------------------------------------------------------------
// Convert theta/phi: fp32 [c][n] -> bf16 hi/lo [n][c]   (transpose + split)
// ---------------------------------------------------------------------------
__global__ __launch_bounds__(256) void convert_tp()
{
    __shared__ float sm[128][65];
    int b = blockIdx.z;
    int pr = blockIdx.y;
    int n0 = blockIdx.x * 64;
    const float* src = d_proj + ((size_t)b * 384 + pr * 128) * NTOK;
    __nv_bfloat16* dh = (pr == 0 ? d_th_hi : d_ph_hi);
    __nv_bfloat16* dl = (pr == 0 ? d_th_lo : d_ph_lo);
    int tid = threadIdx.x;

    #pragma unroll
    for (int it = 0; it < 8; it++) {
        int idx = tid + it * 256;
        int c = idx >> 4, n = (idx & 15) * 4;
        float4 v = *(const float4*)&src[(size_t)c * NTOK + n0 + n];
        sm[c][n+0] = v.x; sm[c][n+1] = v.y; sm[c][n+2] = v.z; sm[c][n+3] = v.w;
    }
    __syncthreads();
    #pragma unroll
    for (int it = 0; it < 16; it++) {
        int idx = tid + it * 256;
        int t = idx >> 6, cp = idx & 63;
        int c = cp * 2;
        float v0 = sm[c][t], v1 = sm[c+1][t];
        __nv_bfloat16 h0 = __float2bfloat16(v0), h1 = __float2bfloat16(v1);
        __nv_bfloat162 hp; hp.x = h0; hp.y = h1;
        __nv_bfloat162 lp = __floats2bfloat162_rn(v0 - __bfloat162float(h0),
                                                  v1 - __bfloat162float(h1));
        size_t base = ((size_t)b * NTOK + n0 + t) * COC + c;
        *(__nv_bfloat162*)&dh[base] = hp;
        *(__nv_bfloat162*)&dl[base] = lp;
    }
}

// ---------------------------------------------------------------------------
// Convert g: fp32 [co][n] -> bf16 hi/lo [co][n]   (split only)
// ---------------------------------------------------------------------------
__global__ __launch_bounds__(256) void convert_g()
{
    size_t e0 = ((size_t)blockIdx.x * 256 + threadIdx.x) * 8;
    int b = (int)(e0 >> 19);
    size_t within = e0 & 524287;
    const float* s = d_proj + (size_t)b * 1572864 + 1048576 + within;
    float v[8];
    *(float4*)&v[0] = *(const float4*)&s[0];
    *(float4*)&v[4] = *(const float4*)&s[4];
    uint32_t h[4], l[4];
    #pragma unroll
    for (int i = 0; i < 4; i++) {
        __nv_bfloat16 h0 = __float2bfloat16(v[2*i]), h1 = __float2bfloat16(v[2*i+1]);
        __nv_bfloat162 hp; hp.x = h0; hp.y = h1;
        __nv_bfloat162 lp = __floats2bfloat162_rn(v[2*i] - __bfloat162float(h0),
                                                  v[2*i+1] - __bfloat162float(h1));
        h[i] = *(uint32_t*)&hp; l[i] = *(uint32_t*)&lp;
    }
    *(uint4*)&d_g_hi[e0] = make_uint4(h[0], h[1], h[2], h[3]);
    *(uint4*)&d_g_lo[e0] = make_uint4(l[0], l[1], l[2], l[3]);
}

// ---------------------------------------------------------------------------
// Flash attention via mma.sync bf16 hi/lo 3-split, fixed-shift softmax.
// ---------------------------------------------------------------------------
#define SM_TH_HI  0u
#define SM_TH_LO  34816u
#define SM_PH     69632u
#define SM_G      139264u
#define SM_LARR   212992u
#define SM_BYTES  213504

__global__ __launch_bounds__(256, 1) void attn_kernel()
{
    extern __shared__ char sm[];
    uint32_t sb = smem_u32(sm);
    int tid = threadIdx.x, w = tid >> 5, lane = tid & 31;
    int b = blockIdx.y, q0 = blockIdx.x * BQ;

    const __nv_bfloat16* thh = d_th_hi + ((size_t)b * NTOK + q0) * COC;
    const __nv_bfloat16* thl = d_th_lo + ((size_t)b * NTOK + q0) * COC;
    const __nv_bfloat16* phh = d_ph_hi + (size_t)b * NTOK * COC;
    const __nv_bfloat16* phl = d_ph_lo + (size_t)b * NTOK * COC;
    const __nv_bfloat16* ghh = d_g_hi + (size_t)b * COC * NTOK;
    const __nv_bfloat16* ghl = d_g_lo + (size_t)b * COC * NTOK;

    #pragma unroll
    for (int it = 0; it < 8; it++) {
        int idx = tid + it * 256;
        int r = idx >> 4, ch = idx & 15;
        uint32_t d1 = sb + SM_TH_HI + r * 272 + ch * 16;
        CPA(d1,         thh + (size_t)r * COC + ch * 8);
        CPA(d1 + 34816, thl + (size_t)r * COC + ch * 8);
    }
    #pragma unroll
    for (int it = 0; it < 4; it++) {
        int idx = tid + it * 256;
        int r = idx >> 4, ch = idx & 15;
        uint32_t d1 = sb + SM_PH + r * 272 + ch * 16;
        CPA(d1,         phh + (size_t)r * COC + ch * 8);
        CPA(d1 + 17408, phl + (size_t)r * COC + ch * 8);
        int r2 = idx >> 3, ch2 = idx & 7;
        uint32_t d2 = sb + SM_G + r2 * 144 + ch2 * 16;
        CPA(d2,         ghh + (size_t)r2 * NTOK + ch2 * 8);
        CPA(d2 + 18432, ghl + (size_t)r2 * NTOK + ch2 * 8);
    }
    CPC();

    float oacc[16][4];
    #pragma unroll
    for (int i = 0; i < 16; i++)
        #pragma unroll
        for (int j = 0; j < 4; j++) oacc[i][j] = 0.f;
    float lsum0 = 0.f, lsum1 = 0.f;

    uint32_t aaddrH = sb + SM_TH_HI + (16*w + (lane & 15)) * 272 + ((lane >> 4) & 1) * 16;
    uint32_t aaddrL = aaddrH + 34816;
    uint32_t bRow   = (lane & 7) + ((lane & 16) >> 1);
    uint32_t bColB  = (lane & 8) * 2;

    for (int kt = 0; kt < NKT; kt++) {
        if (kt + 1 < NKT) {
            int buf = (kt + 1) & 1;
            int k0 = (kt + 1) * BK;
            uint32_t phB = sb + SM_PH + buf * 34816u;
            uint32_t gB  = sb + SM_G  + buf * 36864u;
            #pragma unroll
            for (int it = 0; it < 4; it++) {
                int idx = tid + it * 256;
                int r = idx >> 4, ch = idx & 15;
                uint32_t d1 = phB + r * 272 + ch * 16;
                CPA(d1,         phh + (size_t)(k0 + r) * COC + ch * 8);
                CPA(d1 + 17408, phl + (size_t)(k0 + r) * COC + ch * 8);
                int r2 = idx >> 3, ch2 = idx & 7;
                uint32_t d2 = gB + r2 * 144 + ch2 * 16;
                CPA(d2,         ghh + (size_t)r2 * NTOK + k0 + ch2 * 8);
                CPA(d2 + 18432, ghl + (size_t)r2 * NTOK + k0 + ch2 * 8);
            }
            CPC();
            CPW1();
        } else {
            CPW0();
        }
        __syncthreads();

        int buf = kt & 1;
        uint32_t phH = sb + SM_PH + buf * 34816u;
        uint32_t phL = phH + 17408u;
        uint32_t gH  = sb + SM_G + buf * 36864u;
        uint32_t gL  = gH + 18432u;

        float sacc[8][4];
        #pragma unroll
        for (int i = 0; i < 8; i++)
            #pragma unroll
            for (int j = 0; j < 4; j++) sacc[i][j] = 0.f;

        #pragma unroll
        for (int kc = 0; kc < 8; kc++) {
            uint32_t ah[4], al[4];
            ldsm4(ah, aaddrH + kc * 32);
            ldsm4(al, aaddrL + kc * 32);
            #pragma unroll
            for (int np = 0; np < 4; np++) {
                uint32_t bh[4], bl[4];
                uint32_t ba = (16 * np + bRow) * 272 + bColB + kc * 32;
                ldsm4(bh, phH + ba);
                ldsm4(bl, phL + ba);
                mma16816(sacc[2*np],   ah, bh[0], bh[1]);
                mma16816(sacc[2*np+1], ah, bh[2], bh[3]);
                mma16816(sacc[2*np],   ah, bl[0], bl[1]);
                mma16816(sacc[2*np+1], ah, bl[2], bl[3]);
                mma16816(sacc[2*np],   al, bh[0], bh[1]);
                mma16816(sacc[2*np+1], al, bh[2], bh[3]);
            }
        }

        #pragma unroll
        for (int nf = 0; nf < 8; nf++) {
            float e0 = __expf(sacc[nf][0] - 40.f);
            float e1 = __expf(sacc[nf][1] - 40.f);
            float e2 = __expf(sacc[nf][2] - 40.f);
            float e3 = __expf(sacc[nf][3] - 40.f);
            sacc[nf][0] = e0; sacc[nf][1] = e1; sacc[nf][2] = e2; sacc[nf][3] = e3;
            lsum0 += e0 + e1;
            lsum1 += e2 + e3;
        }
        uint32_t APh[4][4], APl[4][4];
        #pragma unroll
        for (int kc = 0; kc < 4; kc++) {
            #pragma unroll
            for (int half = 0; half < 2; half++) {
                {
                    float p0 = sacc[2*kc][half*2], p1 = sacc[2*kc][half*2+1];
                    __nv_bfloat16 h0 = __float2bfloat16(p0), h1 = __float2bfloat16(p1);
                    __nv_bfloat162 hp; hp.x = h0; hp.y = h1;
                    APh[kc][half] = *(uint32_t*)&hp;
                    APl[kc][half] = pack_bf16_hi(p0 - __bfloat162float(h0),
                                                 p1 - __bfloat162float(h1));
                }
                {
                    float p0 = sacc[2*kc+1][half*2], p1 = sacc[2*kc+1][half*2+1];
                    __nv_bfloat16 h0 = __float2bfloat16(p0), h1 = __float2bfloat16(p1);
                    __nv_bfloat162 hp; hp.x = h0; hp.y = h1;
                    APh[kc][2+half] = *(uint32_t*)&hp;
                    APl[kc][2+half] = pack_bf16_hi(p0 - __bfloat162float(h0),
                                                   p1 - __bfloat162float(h1));
                }
            }
        }

        #pragma unroll
        for (int kc = 0; kc < 4; kc++) {
            #pragma unroll
            for (int np = 0; np < 8; np++) {
                uint32_t bh[4], bl[4];
                uint32_t ba = (16 * np + bRow) * 144 + bColB + kc * 32;
                ldsm4(bh, gH + ba);
                ldsm4(bl, gL + ba);
                mma16816(oacc[2*np],   APh[kc], bh[0], bh[1]);
                mma16816(oacc[2*np+1], APh[kc], bh[2], bh[3]);
                mma16816(oacc[2*np],   APh[kc], bl[0], bl[1]);
                mma16816(oacc[2*np+1], APh[kc], bl[2], bl[3]);
                mma16816(oacc[2*np],   APl[kc], bh[0], bh[1]);
                mma16816(oacc[2*np+1], APl[kc], bh[2], bh[3]);
            }
        }
        __syncthreads();
    }

    lsum0 += __shfl_xor_sync(0xffffffffu, lsum0, 1);
    lsum0 += __shfl_xor_sync(0xffffffffu, lsum0, 2);
    lsum1 += __shfl_xor_sync(0xffffffffu, lsum1, 1);
    lsum1 += __shfl_xor_sync(0xffffffffu, lsum1, 2);
    float* larr = (float*)(sm + SM_LARR);
    int gr = lane >> 2, ct = lane & 3;
    if (ct == 0) {
        larr[16*w + gr]     = lsum0;
        larr[16*w + gr + 8] = lsum1;
    }
    __syncthreads();
    float linv0 = 1.f / larr[16*w + gr];
    float linv1 = 1.f / larr[16*w + gr + 8];

    float* Ys = (float*)sm;
    #pragma unroll
    for (int nf = 0; nf < 16; nf++) {
        int co = 8 * nf + 2 * ct;
        int q  = 16 * w + gr;
        Ys[co * 132 + q]           = oacc[nf][0] * linv0;
        Ys[(co + 1) * 132 + q]     = oacc[nf][1] * linv0;
        Ys[co * 132 + q + 8]       = oacc[nf][2] * linv1;
        Ys[(co + 1) * 132 + q + 8] = oacc[nf][3] * linv1;
    }
    __syncthreads();
    float* yout = d_y + (size_t)b * COC * NTOK;
    #pragma unroll
    for (int it = 0; it < 16; it++) {
        int idx = tid + it * 256;
        int row = idx >> 5, c4 = (idx & 31) * 4;
        *(float4*)&yout[(size_t)row * NTOK + q0 + c4] = *(float4*)&Ys[row * 132 + c4];
    }
}

// ---------------------------------------------------------------------------
// Output GEMM + bias + residual
// ---------------------------------------------------------------------------
__global__ __launch_bounds__(256) void out_kernel(
    const float* __restrict__ wW, const float* __restrict__ bW,
    const float* __restrict__ x, float* __restrict__ z)
{
    __shared__ float As[16][64];
    __shared__ float Bs[16][64];
    int b    = blockIdx.z;
    int row0 = blockIdx.y * 64;
    int n0   = blockIdx.x * 64;
    int tid = threadIdx.x, ty = tid >> 4, tx = tid & 15;
    const float* Y = d_y + (size_t)b * COC * NTOK;

    float acc[4][4] = {};
    int am = tid >> 2,  ak = (tid & 3) * 4;
    int bk = tid >> 4,  bn = (tid & 15) * 4;

    for (int k0 = 0; k0 < COC; k0 += 16) {
        float4 av = *(const float4*)&wW[(row0 + am) * COC + k0 + ak];
        As[ak+0][am] = av.x; As[ak+1][am] = av.y;
        As[ak+2][am] = av.z; As[ak+3][am] = av.w;
        *(float4*)&Bs[bk][bn] = *(const float4*)&Y[(size_t)(k0 + bk) * NTOK + n0 + bn];
        __syncthreads();
        #pragma unroll
        for (int kk = 0; kk < 16; kk++) {
            float4 a = *(float4*)&As[kk][ty * 4];
            float4 v = *(float4*)&Bs[kk][tx * 4];
            acc[0][0] += a.x*v.x; acc[0][1] += a.x*v.y; acc[0][2] += a.x*v.z; acc[0][3] += a.x*v.w;
            acc[1][0] += a.y*v.x; acc[1][1] += a.y*v.y; acc[1][2] += a.y*v.z; acc[1][3] += a.y*v.w;
            acc[2][0] += a.z*v.x; acc[2][1] += a.z*v.y; acc[2][2] += a.z*v.z; acc[2][3] += a.z*v.w;
            acc[3][0] += a.w*v.x; acc[3][1] += a.w*v.y; acc[3][2] += a.w*v.z; acc[3][3] += a.w*v.w;
        }
        __syncthreads();
    }
    #pragma unroll
    for (int i = 0; i < 4; i++) {
        int r = row0 + ty * 4 + i;
        float bv = bW[r];
        float4 xv = *(const float4*)&x[((size_t)b * CINC + r) * NTOK + n0 + tx * 4];
        float4 o = make_float4(acc[i][0] + bv + xv.x, acc[i][1] + bv + xv.y,
                               acc[i][2] + bv + xv.z, acc[i][3] + bv + xv.w);
        *(float4*)&z[((size_t)b * CINC + r) * NTOK + n0 + tx * 4] = o;
    }
}

// ---------------------------------------------------------------------------
extern "C" void kernel_launch(void* const* d_in, const int* in_sizes, int n_in,
                              void* d_out, int out_size)
{
    const float* x  = (const float*)d_in[0];
    const float* wt = (const float*)d_in[1];
    const float* bt = (const float*)d_in[2];
    const float* wp = (const float*)d_in[3];
    const float* bp = (const float*)d_in[4];
    const float* wg = (const float*)d_in[5];
    const float* bg = (const float*)d_in[6];
    const float* wW = (const float*)d_in[7];
    const float* bW = (const float*)d_in[8];
    float* z = (float*)d_out;

    static int once = 0;
    if (!once) {
        cudaFuncSetAttribute(attn_kernel, cudaFuncAttributeMaxDynamicSharedMemorySize, SM_BYTES);
        cudaFuncSetAttribute(gemm_proj, cudaFuncAttributeMaxDynamicSharedMemorySize, 49152);
        once = 1;
    }

    wsplit<<<384, 256>>>(wt, wp, wg);
    xsplit<<<dim3(64, 2, 4), 256>>>(x);
    gemm_proj<<<dim3(32, 3, 4), 256, 49152>>>(bt, bp, bg);
    convert_tp<<<dim3(64, 2, 4), 256>>>();
    convert_g<<<1024, 256>>>();
    attn_kernel<<<dim3(NTOK / BQ, 4), 256, SM_BYTES>>>();
    out_kernel<<<dim3(64, 4, 4), 256>>>(wW, bW, x, z);
}